// round 2
// baseline (speedup 1.0000x reference)
#include <cuda_runtime.h>

// out: [16384, 2046] f32 = tanh(row) broadcast over batch; row depends only on
// kernel_weights[6]. values input is unused (shape-only in the reference).
#define BS       16384
#define L_OUT    2046
#define GROUPS   (BS / 2)          // 8192 two-row groups
#define F4_PER_G 1023              // 4092 floats per group = 1023 float4
#define TPB      256
#define COL_BLK  4                 // 4*256 = 1024 threads cover 1023 f4 slots
#define G_CHUNKS 128               // groups split across blockIdx.y
#define G_PER_B  (GROUPS / G_CHUNKS)  // 64 stores per thread

#define NEG_LOG_NORM 1.3836465597893728f   // -log(0.1*sqrt(2*pi))
#define INV_STD      10.0f

__device__ __forceinline__ float row_value(int c, const float* __restrict__ w) {
    const float means[6] = {0.0f, 0.2f, 0.4f, 0.6f, 0.8f, 1.0f};
    float pos = (float)c / (float)L_OUT;
    float acc = 0.0f;
#pragma unroll
    for (int k = 0; k < 6; k++) {
        float z = (pos - means[k]) * INV_STD;
        float pdf = expf(fmaf(-0.5f * z, z, NEG_LOG_NORM));
        acc = fmaf(w[k], pdf, acc);
    }
    return tanhf(acc);
}

__global__ void __launch_bounds__(TPB) bcast_kernel(const float* __restrict__ kw,
                                                    float4* __restrict__ out) {
    int t = blockIdx.x * TPB + threadIdx.x;    // float4 slot within a 2-row group
    if (t >= F4_PER_G) return;                  // 1 of 1024 threads idles

    float w[6];
#pragma unroll
    for (int k = 0; k < 6; k++) w[k] = 0.25f * tanhf(__ldg(&kw[k]));

    // Columns for this slot (wrap across the row boundary inside the group)
    int e = 4 * t;
    int c0 = e;     if (c0 >= L_OUT) c0 -= L_OUT;
    int c1 = e + 1; if (c1 >= L_OUT) c1 -= L_OUT;
    int c2 = e + 2; if (c2 >= L_OUT) c2 -= L_OUT;
    int c3 = e + 3; if (c3 >= L_OUT) c3 -= L_OUT;

    float4 v;
    v.x = row_value(c0, w);
    v.y = row_value(c1, w);
    v.z = row_value(c2, w);
    v.w = row_value(c3, w);

    size_t g0 = (size_t)blockIdx.y * G_PER_B;
    float4* p = out + g0 * F4_PER_G + t;
#pragma unroll 8
    for (int g = 0; g < G_PER_B; g++) {
        __stcs(p, v);         // streaming store: never re-read, evict-first
        p += F4_PER_G;
    }
}

extern "C" void kernel_launch(void* const* d_in, const int* in_sizes, int n_in,
                              void* d_out, int out_size) {
    const float* kw = (const float*)d_in[1];   // kernel_weights [6]
    dim3 grid(COL_BLK, G_CHUNKS);              // 512 blocks, 256 threads
    bcast_kernel<<<grid, TPB>>>(kw, (float4*)d_out);
}